// round 11
// baseline (speedup 1.0000x reference)
#include <cuda_runtime.h>
#include <cuda_bf16.h>
#include <cuda_fp16.h>
#include <cstdint>

#define NPIX 4096
#define CIN  512
#define B    4

__device__ __align__(16) __nv_bfloat16 g_xT[(size_t)B * NPIX * CIN];   // [b][n][c]
__device__ __align__(16) __half        g_q [(size_t)B * NPIX * 64];    // [b][n][d] f16
__device__ __align__(16) __half        g_k [(size_t)B * NPIX * 64];    // [b][n][d] f16
__device__ __align__(16) __half        g_v [(size_t)B * NPIX * CIN];   // [b][n][c] f16
__device__ __align__(16) __nv_bfloat16 g_wqk[128 * CIN];               // [q64;k64][c]
__device__ __align__(16) __nv_bfloat16 g_wv [CIN * CIN];               // [o][c]

// ------------------------------ helpers -----------------------------------
__device__ __forceinline__ uint32_t smem_u32(const void* p) {
    uint32_t a;
    asm("{ .reg .u64 t; cvta.to.shared.u64 t, %1; cvt.u32.u64 %0, t; }" : "=r"(a) : "l"(p));
    return a;
}
__device__ __forceinline__ void ldsm_x4(uint32_t* r, uint32_t a) {
    asm volatile("ldmatrix.sync.aligned.m8n8.x4.shared.b16 {%0,%1,%2,%3}, [%4];"
        : "=r"(r[0]), "=r"(r[1]), "=r"(r[2]), "=r"(r[3]) : "r"(a));
}
__device__ __forceinline__ void ldsm_x4t(uint32_t* r, uint32_t a) {
    asm volatile("ldmatrix.sync.aligned.m8n8.x4.trans.shared.b16 {%0,%1,%2,%3}, [%4];"
        : "=r"(r[0]), "=r"(r[1]), "=r"(r[2]), "=r"(r[3]) : "r"(a));
}
// bf16 x bf16 -> f32 (proj)
__device__ __forceinline__ void mma_bf16(float* d, const uint32_t* a, const uint32_t* b) {
    asm volatile("mma.sync.aligned.m16n8k16.row.col.f32.bf16.bf16.f32 "
        "{%0,%1,%2,%3},{%4,%5,%6,%7},{%8,%9},{%0,%1,%2,%3};"
        : "+f"(d[0]), "+f"(d[1]), "+f"(d[2]), "+f"(d[3])
        : "r"(a[0]), "r"(a[1]), "r"(a[2]), "r"(a[3]), "r"(b[0]), "r"(b[1]));
}
// f16 x f16 -> f32 (S and O gemms)
__device__ __forceinline__ void mma_f16f32(float* d, const uint32_t* a, const uint32_t* b) {
    asm volatile("mma.sync.aligned.m16n8k16.row.col.f32.f16.f16.f32 "
        "{%0,%1,%2,%3},{%4,%5,%6,%7},{%8,%9},{%0,%1,%2,%3};"
        : "+f"(d[0]), "+f"(d[1]), "+f"(d[2]), "+f"(d[3])
        : "r"(a[0]), "r"(a[1]), "r"(a[2]), "r"(a[3]), "r"(b[0]), "r"(b[1]));
}
__device__ __forceinline__ void cp16(uint32_t dst, const void* src) {
    asm volatile("cp.async.cg.shared.global [%0], [%1], 16;" :: "r"(dst), "l"(src));
}
#define CP_COMMIT() asm volatile("cp.async.commit_group;" ::: "memory")
#define CP_WAIT0()  asm volatile("cp.async.wait_group 0;" ::: "memory")
__device__ __forceinline__ uint32_t pack_h2(float lo, float hi) {
    uint32_t u;
    asm("cvt.rn.f16x2.f32 %0, %1, %2;" : "=r"(u) : "f"(hi), "f"(lo));
    return u;
}

// -------------------------- prep kernels ----------------------------------
__global__ void convert_w_kernel(const float* __restrict__ Wq, const float* __restrict__ Wk,
                                 const float* __restrict__ Wv) {
    int i = blockIdx.x * 256 + threadIdx.x;
    if (i < 64 * CIN) g_wqk[i] = __float2bfloat16(Wq[i]);
    else if (i < 128 * CIN) g_wqk[i] = __float2bfloat16(Wk[i - 64 * CIN]);
    else if (i < 128 * CIN + CIN * CIN) g_wv[i - 128 * CIN] = __float2bfloat16(Wv[i - 128 * CIN]);
}

__global__ __launch_bounds__(256)
void transpose_x_kernel(const float* __restrict__ x) {
    __shared__ float s[64][65];
    const int n0 = blockIdx.x * 64, c0 = blockIdx.y * 64, b = blockIdx.z;
    const float* xb = x + ((size_t)b * CIN + c0) * NPIX + n0;
    for (int i = threadIdx.x; i < 64 * 64; i += 256) {
        int c = i >> 6, n = i & 63;
        s[c][n] = xb[(size_t)c * NPIX + n];
    }
    __syncthreads();
    __nv_bfloat16* dst = g_xT + ((size_t)b * NPIX + n0) * CIN + c0;
    for (int i = threadIdx.x; i < 64 * 32; i += 256) {
        int n = i >> 5, c2 = (i & 31) * 2;
        *reinterpret_cast<__nv_bfloat162*>(dst + (size_t)n * CIN + c2) =
            __float22bfloat162_rn(make_float2(s[c2][n], s[c2 + 1][n]));
    }
}

// ---------------- fused proj: C[n(128), out(128)] = xT . W^T --------------
__global__ __launch_bounds__(256)
void proj_qkv_kernel(const float* __restrict__ bq, const float* __restrict__ bk,
                     const float* __restrict__ bv) {
    extern __shared__ char dsm[];
    const uint32_t sb = smem_u32(dsm);
    const uint32_t SA = sb, SB = sb + 36864;
    const int tid = threadIdx.x, wid = tid >> 5, lane = tid & 31;
    const int n0 = blockIdx.x * 128, chunk = blockIdx.y, b = blockIdx.z;
    const __nv_bfloat16* gA = g_xT + ((size_t)b * NPIX + n0) * CIN;
    const __nv_bfloat16* gB = (chunk == 0) ? g_wqk : (g_wv + (size_t)(chunk - 1) * 128 * CIN);

    auto ldA = [&](uint32_t dst, int kk) {
        for (int i = tid; i < 1024; i += 256) {
            int r = i >> 3, s = i & 7;
            cp16(dst + r * 144 + s * 16, gA + (size_t)r * CIN + kk * 64 + s * 8);
        }
    };
    auto ldB = [&](uint32_t dst, int kk) {
        for (int i = tid; i < 1024; i += 256) {
            int r = i >> 3, s = i & 7;
            cp16(dst + r * 144 + s * 16, gB + (size_t)r * CIN + kk * 64 + s * 8);
        }
    };
    ldA(SA, 0); ldB(SB, 0); CP_COMMIT(); CP_WAIT0(); __syncthreads();

    const int ar = (lane & 7) + ((lane >> 3) & 1) * 8, ak = ((lane >> 4) & 1) * 8;
    const int bn = ((lane >> 4) & 1) * 8 + (lane & 7), bk2 = ((lane >> 3) & 1) * 8;
    float o[16][4] = {};

    for (int kk = 0; kk < 8; kk++) {
        const int buf = kk & 1;
        if (kk < 7) { ldA(SA + (buf ^ 1) * 18432, kk + 1); ldB(SB + (buf ^ 1) * 18432, kk + 1); CP_COMMIT(); }
        const uint32_t Ab = SA + buf * 18432 + (16 * wid + ar) * 144 + ak * 2;
        const uint32_t Bb = SB + buf * 18432;
        uint32_t qa[4][4];
        #pragma unroll
        for (int kc = 0; kc < 4; kc++) ldsm_x4(qa[kc], Ab + kc * 32);
        #pragma unroll
        for (int ot2 = 0; ot2 < 8; ot2++) {
            #pragma unroll
            for (int kc = 0; kc < 4; kc++) {
                uint32_t br[4];
                ldsm_x4(br, Bb + (ot2 * 16 + bn) * 144 + (kc * 16 + bk2) * 2);
                mma_bf16(o[ot2 * 2],     qa[kc], br);
                mma_bf16(o[ot2 * 2 + 1], qa[kc], br + 2);
            }
        }
        if (kk < 7) CP_WAIT0();
        __syncthreads();
    }

    const int r0 = 16 * wid + (lane >> 2);
    if (chunk == 0) {
        #pragma unroll
        for (int ot = 0; ot < 16; ot++) {
            int oc = ot * 8 + (lane & 3) * 2;
            const float* bias = (oc < 64) ? bq : bk;
            int oo = oc & 63;
            float b0 = __ldg(bias + oo), b1 = __ldg(bias + oo + 1);
            __half* base = (oc < 64) ? g_q : g_k;
            uint32_t* d0 = reinterpret_cast<uint32_t*>(base + ((size_t)b * NPIX + n0 + r0) * 64 + oo);
            uint32_t* d1 = reinterpret_cast<uint32_t*>(base + ((size_t)b * NPIX + n0 + r0 + 8) * 64 + oo);
            *d0 = pack_h2(o[ot][0] + b0, o[ot][1] + b1);
            *d1 = pack_h2(o[ot][2] + b0, o[ot][3] + b1);
        }
    } else {
        const int c0 = (chunk - 1) * 128;
        #pragma unroll
        for (int ot = 0; ot < 16; ot++) {
            int c = c0 + ot * 8 + (lane & 3) * 2;
            float b0 = __ldg(bv + c), b1 = __ldg(bv + c + 1);
            uint32_t* d0 = reinterpret_cast<uint32_t*>(g_v + ((size_t)b * NPIX + n0 + r0) * CIN + c);
            uint32_t* d1 = reinterpret_cast<uint32_t*>(g_v + ((size_t)b * NPIX + n0 + r0 + 8) * CIN + c);
            *d0 = pack_h2(o[ot][0] + b0, o[ot][1] + b1);
            *d1 = pack_h2(o[ot][2] + b0, o[ot][3] + b1);
        }
    }
}

// --------------------------- fused attention ------------------------------
// CTA: 64 m x 128 c-quarter x b (grid 64x4x4 = 1024). 128 threads = 4 warps,
// each 16m x 128c (o = 64 f32 regs). __launch_bounds__(128,4) -> 4 CTAs/SM,
// 16 warps. smem 52 KB x 4 = 208 KB/SM.
// [SQK1 9216 | SK0 9216 | SV 2x17408]; Q smem recycled as K buf 1.
// Epilogue reuses smem as f32 epi[64][129].
__global__ __launch_bounds__(128, 4)
void attn_kernel(const float* __restrict__ x, float* __restrict__ out) {
    extern __shared__ char dsm[];
    const uint32_t sb = smem_u32(dsm);
    const uint32_t SQK1 = sb, SK0 = sb + 9216, SV = sb + 18432;
    const int tid = threadIdx.x, wid = tid >> 5, lane = tid & 31;
    const int m0 = blockIdx.x * 64, cq = blockIdx.y, b = blockIdx.z;

    const __half* gQ = g_q + ((size_t)b * NPIX + m0) * 64;

    // incremented source pointers (register diet vs per-iter jj*stride)
    const __half* srcK = g_k + (size_t)b * NPIX * 64;
    const __half* srcV = g_v + (size_t)b * NPIX * CIN + cq * 128;

    const int kr = tid >> 3, ks = tid & 7;     // K loader: 16B chunks, 64x64 tile
    const int vr = tid >> 3, vs = tid & 7;     // V loader: 64x128 tile, 8 chunks/row
    // K tile: 512 chunks / 128 thr = 4 per thread (rows kr, kr+16, kr+32, kr+48)
    // V tile: 1024 chunks / 128 thr = 8 per thread
    auto ldK = [&](uint32_t dst, const __half* src) {
        #pragma unroll
        for (int t = 0; t < 4; t++)
            cp16(dst + (kr + t * 16) * 144 + ks * 16, src + (size_t)(kr + t * 16) * 64 + ks * 8);
    };
    auto ldV = [&](uint32_t dst, const __half* src) {
        #pragma unroll
        for (int t = 0; t < 4; t++) {
            cp16(dst + (vr + t * 16) * 272 + vs * 16,
                 src + (size_t)(vr + t * 16) * CIN + vs * 8);
            cp16(dst + (vr + t * 16) * 272 + (vs + 8) * 16,
                 src + (size_t)(vr + t * 16) * CIN + (vs + 8) * 8);
        }
    };
    // prologue: Q (64m x 64d into SQK1), K0, V0
    #pragma unroll
    for (int t = 0; t < 4; t++)
        cp16(SQK1 + (kr + t * 16) * 144 + ks * 16, gQ + (size_t)(kr + t * 16) * 64 + ks * 8);
    ldK(SK0, srcK); ldV(SV, srcV);
    CP_COMMIT(); CP_WAIT0(); __syncthreads();

    const int ar = (lane & 7) + ((lane >> 3) & 1) * 8, ak = ((lane >> 4) & 1) * 8;
    const int bn = ((lane >> 4) & 1) * 8 + (lane & 7), bk2 = ((lane >> 3) & 1) * 8;
    const int vn = ((lane >> 3) & 1) * 8 + (lane & 7), vc = ((lane >> 4) & 1) * 8;

    // hoist Q fragments; Q smem becomes K buffer 1
    uint32_t qa[4][4];
    {
        const uint32_t Ab = SQK1 + (wid * 16 + ar) * 144 + ak * 2;
        #pragma unroll
        for (int kc = 0; kc < 4; kc++) ldsm_x4(qa[kc], Ab + kc * 32);
    }
    __syncthreads();

    float o[16][4] = {};
    float rs[2] = {};

    for (int j = 0; j < 64; j++) {
        const int buf = j & 1;
        const uint32_t Kb = buf ? SQK1 : SK0;
        const uint32_t Vb = SV + buf * 17408;
        if (j < 63) {
            srcK += 64 * 64;
            srcV += 64 * CIN;
            ldK(buf ? SK0 : SQK1, srcK);
            ldV(SV + (buf ^ 1) * 17408, srcV);
            CP_COMMIT();
        }
        #pragma unroll
        for (int nt = 0; nt < 4; nt++) {
            // S = Q.K^T (16m x 16n)
            float s[8] = {};
            #pragma unroll
            for (int kc = 0; kc < 4; kc++) {
                uint32_t br[4];
                ldsm_x4(br, Kb + (nt * 16 + bn) * 144 + (kc * 16 + bk2) * 2);
                mma_f16f32(s,     qa[kc], br);
                mma_f16f32(s + 4, qa[kc], br + 2);
            }
            // exp + rowsum + pack
            #pragma unroll
            for (int t = 0; t < 8; t++) s[t] = __expf(s[t]);
            rs[0] += s[0] + s[1] + s[4] + s[5];
            rs[1] += s[2] + s[3] + s[6] + s[7];
            uint32_t pa[4];
            pa[0] = pack_h2(s[0], s[1]);
            pa[1] = pack_h2(s[2], s[3]);
            pa[2] = pack_h2(s[4], s[5]);
            pa[3] = pack_h2(s[6], s[7]);
            // O += P.V^T over 128 c
            #pragma unroll
            for (int ct = 0; ct < 8; ct++) {
                uint32_t vfr[4];
                ldsm_x4t(vfr, Vb + (nt * 16 + vn) * 272 + (ct * 16 + vc) * 2);
                mma_f16f32(o[ct * 2],     pa, vfr);
                mma_f16f32(o[ct * 2 + 1], pa, vfr + 2);
            }
        }
        if (j < 63) CP_WAIT0();
        __syncthreads();
    }

    // quad-lane rowsum reduce
    float inv[2];
    #pragma unroll
    for (int h = 0; h < 2; h++) {
        float r = rs[h];
        r += __shfl_xor_sync(0xffffffffu, r, 1);
        r += __shfl_xor_sync(0xffffffffu, r, 2);
        inv[h] = 1.0f / r;
    }

    // epilogue: transpose through smem, out[b][c][m] = O/sum + x
    float* epi = reinterpret_cast<float*>(dsm);
    const int r0 = wid * 16 + (lane >> 2);
    #pragma unroll
    for (int ot = 0; ot < 16; ot++) {
        int c = ot * 8 + (lane & 3) * 2;
        epi[r0 * 129 + c]           = o[ot][0] * inv[0];
        epi[r0 * 129 + c + 1]       = o[ot][1] * inv[0];
        epi[(r0 + 8) * 129 + c]     = o[ot][2] * inv[1];
        epi[(r0 + 8) * 129 + c + 1] = o[ot][3] * inv[1];
    }
    __syncthreads();
    const float* xb = x + (size_t)b * CIN * NPIX;
    float* ob = out + (size_t)b * CIN * NPIX;
    for (int i = tid; i < 128 * 64; i += 128) {
        int c = i >> 6, m = i & 63;
        size_t gidx = (size_t)(cq * 128 + c) * NPIX + m0 + m;
        ob[gidx] = epi[m * 129 + c] + xb[gidx];
    }
}

// ---------------------------------------------------------------------------
extern "C" void kernel_launch(void* const* d_in, const int* in_sizes, int n_in,
                              void* d_out, int out_size)
{
    const float* x  = (const float*)d_in[0];
    const float* Wq = (const float*)d_in[1];
    const float* bq = (const float*)d_in[2];
    const float* Wk = (const float*)d_in[3];
    const float* bk = (const float*)d_in[4];
    const float* Wv = (const float*)d_in[5];
    const float* bv = (const float*)d_in[6];
    float* out = (float*)d_out;

    cudaFuncSetAttribute(proj_qkv_kernel, cudaFuncAttributeMaxDynamicSharedMemorySize, 73728);
    cudaFuncSetAttribute(attn_kernel,     cudaFuncAttributeMaxDynamicSharedMemorySize, 53248);

    convert_w_kernel<<<1280, 256>>>(Wq, Wk, Wv);
    transpose_x_kernel<<<dim3(NPIX / 64, CIN / 64, B), 256>>>(x);
    proj_qkv_kernel<<<dim3(NPIX / 128, 5, B), 256, 73728>>>(bq, bk, bv);
    attn_kernel<<<dim3(NPIX / 64, 4, B), 128, 53248>>>(x, out);
}

// round 12
// speedup vs baseline: 1.1087x; 1.1087x over previous
#include <cuda_runtime.h>
#include <cuda_bf16.h>
#include <cuda_fp16.h>
#include <cstdint>

#define NPIX 4096
#define CIN  512
#define B    4

__device__ __align__(16) __nv_bfloat16 g_xT[(size_t)B * NPIX * CIN];   // [b][n][c]
__device__ __align__(16) __half        g_q [(size_t)B * NPIX * 64];    // [b][n][d] f16
__device__ __align__(16) __half        g_k [(size_t)B * NPIX * 64];    // [b][n][d] f16
__device__ __align__(16) __half        g_v [(size_t)B * NPIX * CIN];   // [b][n][c] f16
__device__ __align__(16) __nv_bfloat16 g_wqk[128 * CIN];               // [q64;k64][c]
__device__ __align__(16) __nv_bfloat16 g_wv [CIN * CIN];               // [o][c]

// ------------------------------ helpers -----------------------------------
__device__ __forceinline__ uint32_t smem_u32(const void* p) {
    uint32_t a;
    asm("{ .reg .u64 t; cvta.to.shared.u64 t, %1; cvt.u32.u64 %0, t; }" : "=r"(a) : "l"(p));
    return a;
}
__device__ __forceinline__ void ldsm_x4(uint32_t* r, uint32_t a) {
    asm volatile("ldmatrix.sync.aligned.m8n8.x4.shared.b16 {%0,%1,%2,%3}, [%4];"
        : "=r"(r[0]), "=r"(r[1]), "=r"(r[2]), "=r"(r[3]) : "r"(a));
}
__device__ __forceinline__ void ldsm_x4t(uint32_t* r, uint32_t a) {
    asm volatile("ldmatrix.sync.aligned.m8n8.x4.trans.shared.b16 {%0,%1,%2,%3}, [%4];"
        : "=r"(r[0]), "=r"(r[1]), "=r"(r[2]), "=r"(r[3]) : "r"(a));
}
// bf16 x bf16 -> f32 (proj)
__device__ __forceinline__ void mma_bf16(float* d, const uint32_t* a, const uint32_t* b) {
    asm volatile("mma.sync.aligned.m16n8k16.row.col.f32.bf16.bf16.f32 "
        "{%0,%1,%2,%3},{%4,%5,%6,%7},{%8,%9},{%0,%1,%2,%3};"
        : "+f"(d[0]), "+f"(d[1]), "+f"(d[2]), "+f"(d[3])
        : "r"(a[0]), "r"(a[1]), "r"(a[2]), "r"(a[3]), "r"(b[0]), "r"(b[1]));
}
// f16 x f16 -> f32 (S and O gemms)
__device__ __forceinline__ void mma_f16f32(float* d, const uint32_t* a, const uint32_t* b) {
    asm volatile("mma.sync.aligned.m16n8k16.row.col.f32.f16.f16.f32 "
        "{%0,%1,%2,%3},{%4,%5,%6,%7},{%8,%9},{%0,%1,%2,%3};"
        : "+f"(d[0]), "+f"(d[1]), "+f"(d[2]), "+f"(d[3])
        : "r"(a[0]), "r"(a[1]), "r"(a[2]), "r"(a[3]), "r"(b[0]), "r"(b[1]));
}
__device__ __forceinline__ void cp16(uint32_t dst, const void* src) {
    asm volatile("cp.async.cg.shared.global [%0], [%1], 16;" :: "r"(dst), "l"(src));
}
#define CP_COMMIT() asm volatile("cp.async.commit_group;" ::: "memory")
#define CP_WAIT0()  asm volatile("cp.async.wait_group 0;" ::: "memory")
__device__ __forceinline__ uint32_t pack_h2(float lo, float hi) {
    uint32_t u;
    asm("cvt.rn.f16x2.f32 %0, %1, %2;" : "=r"(u) : "f"(hi), "f"(lo));
    return u;
}

// -------------------------- prep kernels ----------------------------------
__global__ void convert_w_kernel(const float* __restrict__ Wq, const float* __restrict__ Wk,
                                 const float* __restrict__ Wv) {
    int i = blockIdx.x * 256 + threadIdx.x;
    if (i < 64 * CIN) g_wqk[i] = __float2bfloat16(Wq[i]);
    else if (i < 128 * CIN) g_wqk[i] = __float2bfloat16(Wk[i - 64 * CIN]);
    else if (i < 128 * CIN + CIN * CIN) g_wv[i - 128 * CIN] = __float2bfloat16(Wv[i - 128 * CIN]);
}

__global__ __launch_bounds__(256)
void transpose_x_kernel(const float* __restrict__ x) {
    __shared__ float s[64][65];
    const int n0 = blockIdx.x * 64, c0 = blockIdx.y * 64, b = blockIdx.z;
    const float* xb = x + ((size_t)b * CIN + c0) * NPIX + n0;
    for (int i = threadIdx.x; i < 64 * 64; i += 256) {
        int c = i >> 6, n = i & 63;
        s[c][n] = xb[(size_t)c * NPIX + n];
    }
    __syncthreads();
    __nv_bfloat16* dst = g_xT + ((size_t)b * NPIX + n0) * CIN + c0;
    for (int i = threadIdx.x; i < 64 * 32; i += 256) {
        int n = i >> 5, c2 = (i & 31) * 2;
        *reinterpret_cast<__nv_bfloat162*>(dst + (size_t)n * CIN + c2) =
            __float22bfloat162_rn(make_float2(s[c2][n], s[c2 + 1][n]));
    }
}

// ---------------- fused proj: C[n(128), out(128)] = xT . W^T --------------
__global__ __launch_bounds__(256)
void proj_qkv_kernel(const float* __restrict__ bq, const float* __restrict__ bk,
                     const float* __restrict__ bv) {
    extern __shared__ char dsm[];
    const uint32_t sb = smem_u32(dsm);
    const uint32_t SA = sb, SB = sb + 36864;
    const int tid = threadIdx.x, wid = tid >> 5, lane = tid & 31;
    const int n0 = blockIdx.x * 128, chunk = blockIdx.y, b = blockIdx.z;
    const __nv_bfloat16* gA = g_xT + ((size_t)b * NPIX + n0) * CIN;
    const __nv_bfloat16* gB = (chunk == 0) ? g_wqk : (g_wv + (size_t)(chunk - 1) * 128 * CIN);

    auto ldA = [&](uint32_t dst, int kk) {
        for (int i = tid; i < 1024; i += 256) {
            int r = i >> 3, s = i & 7;
            cp16(dst + r * 144 + s * 16, gA + (size_t)r * CIN + kk * 64 + s * 8);
        }
    };
    auto ldB = [&](uint32_t dst, int kk) {
        for (int i = tid; i < 1024; i += 256) {
            int r = i >> 3, s = i & 7;
            cp16(dst + r * 144 + s * 16, gB + (size_t)r * CIN + kk * 64 + s * 8);
        }
    };
    ldA(SA, 0); ldB(SB, 0); CP_COMMIT(); CP_WAIT0(); __syncthreads();

    const int ar = (lane & 7) + ((lane >> 3) & 1) * 8, ak = ((lane >> 4) & 1) * 8;
    const int bn = ((lane >> 4) & 1) * 8 + (lane & 7), bk2 = ((lane >> 3) & 1) * 8;
    float o[16][4] = {};

    for (int kk = 0; kk < 8; kk++) {
        const int buf = kk & 1;
        if (kk < 7) { ldA(SA + (buf ^ 1) * 18432, kk + 1); ldB(SB + (buf ^ 1) * 18432, kk + 1); CP_COMMIT(); }
        const uint32_t Ab = SA + buf * 18432 + (16 * wid + ar) * 144 + ak * 2;
        const uint32_t Bb = SB + buf * 18432;
        uint32_t qa[4][4];
        #pragma unroll
        for (int kc = 0; kc < 4; kc++) ldsm_x4(qa[kc], Ab + kc * 32);
        #pragma unroll
        for (int ot2 = 0; ot2 < 8; ot2++) {
            #pragma unroll
            for (int kc = 0; kc < 4; kc++) {
                uint32_t br[4];
                ldsm_x4(br, Bb + (ot2 * 16 + bn) * 144 + (kc * 16 + bk2) * 2);
                mma_bf16(o[ot2 * 2],     qa[kc], br);
                mma_bf16(o[ot2 * 2 + 1], qa[kc], br + 2);
            }
        }
        if (kk < 7) CP_WAIT0();
        __syncthreads();
    }

    const int r0 = 16 * wid + (lane >> 2);
    if (chunk == 0) {
        #pragma unroll
        for (int ot = 0; ot < 16; ot++) {
            int oc = ot * 8 + (lane & 3) * 2;
            const float* bias = (oc < 64) ? bq : bk;
            int oo = oc & 63;
            float b0 = __ldg(bias + oo), b1 = __ldg(bias + oo + 1);
            __half* base = (oc < 64) ? g_q : g_k;
            uint32_t* d0 = reinterpret_cast<uint32_t*>(base + ((size_t)b * NPIX + n0 + r0) * 64 + oo);
            uint32_t* d1 = reinterpret_cast<uint32_t*>(base + ((size_t)b * NPIX + n0 + r0 + 8) * 64 + oo);
            *d0 = pack_h2(o[ot][0] + b0, o[ot][1] + b1);
            *d1 = pack_h2(o[ot][2] + b0, o[ot][3] + b1);
        }
    } else {
        const int c0 = (chunk - 1) * 128;
        #pragma unroll
        for (int ot = 0; ot < 16; ot++) {
            int c = c0 + ot * 8 + (lane & 3) * 2;
            float b0 = __ldg(bv + c), b1 = __ldg(bv + c + 1);
            uint32_t* d0 = reinterpret_cast<uint32_t*>(g_v + ((size_t)b * NPIX + n0 + r0) * CIN + c);
            uint32_t* d1 = reinterpret_cast<uint32_t*>(g_v + ((size_t)b * NPIX + n0 + r0 + 8) * CIN + c);
            *d0 = pack_h2(o[ot][0] + b0, o[ot][1] + b1);
            *d1 = pack_h2(o[ot][2] + b0, o[ot][3] + b1);
        }
    }
}

// --------------------------- fused attention ------------------------------
// R4's proven shape, f16 data path. CTA: 128m x 256c-half x b (grid 32x2x4).
// 256 threads = 8 warps, each warp 16m x 256c (o = 128 f32 regs). n-tile 128.
// smem 186 KB: [SQ 18432 | SK 2x18432 | SV 2x67584]; 1 CTA/SM.
// Epilogue reuses smem as f32 epi[128][257].
__global__ __launch_bounds__(256, 1)
void attn_kernel(const float* __restrict__ x, float* __restrict__ out) {
    extern __shared__ char dsm[];
    const uint32_t sb = smem_u32(dsm);
    const uint32_t SQ = sb, SK = sb + 18432, SV = sb + 55296;
    const int tid = threadIdx.x, wid = tid >> 5, lane = tid & 31;
    const int m0 = blockIdx.x * 128, chalf = blockIdx.y, b = blockIdx.z;

    const __half* gQ = g_q + ((size_t)b * NPIX + m0) * 64;
    const __half* gK = g_k + (size_t)b * NPIX * 64;
    const __half* gV = g_v + (size_t)b * NPIX * CIN + chalf * 256;

    auto ldK = [&](uint32_t dst, int jj) {
        const __half* src = gK + (size_t)jj * 128 * 64;
        for (int i = tid; i < 1024; i += 256) {
            int r = i >> 3, s = i & 7;
            cp16(dst + r * 144 + s * 16, src + (size_t)r * 64 + s * 8);
        }
    };
    auto ldV = [&](uint32_t dst, int jj) {
        const __half* src = gV + (size_t)jj * 128 * CIN;
        for (int i = tid; i < 4096; i += 256) {
            int r = i >> 5, s = i & 31;
            cp16(dst + r * 528 + s * 16, src + (size_t)r * CIN + s * 8);
        }
    };
    // prologue: Q + K0 + V0
    for (int i = tid; i < 1024; i += 256) {
        int r = i >> 3, s = i & 7;
        cp16(SQ + r * 144 + s * 16, gQ + (size_t)r * 64 + s * 8);
    }
    ldK(SK, 0); ldV(SV, 0);
    CP_COMMIT(); CP_WAIT0(); __syncthreads();

    const int ar = (lane & 7) + ((lane >> 3) & 1) * 8, ak = ((lane >> 4) & 1) * 8;
    const int bn = ((lane >> 4) & 1) * 8 + (lane & 7), bk2 = ((lane >> 3) & 1) * 8;
    const int vn = ((lane >> 3) & 1) * 8 + (lane & 7), vc = ((lane >> 4) & 1) * 8;

    uint32_t qa[4][4];
    {
        const uint32_t Ab = SQ + (16 * wid + ar) * 144 + ak * 2;
        #pragma unroll
        for (int kc = 0; kc < 4; kc++) ldsm_x4(qa[kc], Ab + kc * 32);
    }

    float o[32][4] = {};
    float rs0 = 0.f, rs1 = 0.f;

    for (int j = 0; j < 32; j++) {
        const int buf = j & 1;
        if (j < 31) { ldK(SK + (buf ^ 1) * 18432, j + 1); ldV(SV + (buf ^ 1) * 67584, j + 1); CP_COMMIT(); }

        // ---- S = Q . K^T, exp, pack to P fragments ----
        const uint32_t Kb = SK + buf * 18432;
        uint32_t pa[8][4];
        #pragma unroll
        for (int nt = 0; nt < 8; nt++) {
            float s0[4] = {}, s1[4] = {};
            #pragma unroll
            for (int kc = 0; kc < 4; kc++) {
                uint32_t br[4];
                ldsm_x4(br, Kb + (nt * 16 + bn) * 144 + (kc * 16 + bk2) * 2);
                mma_f16f32(s0, qa[kc], br);
                mma_f16f32(s1, qa[kc], br + 2);
            }
            #pragma unroll
            for (int t = 0; t < 4; t++) { s0[t] = __expf(s0[t]); s1[t] = __expf(s1[t]); }
            rs0 += s0[0] + s0[1] + s1[0] + s1[1];
            rs1 += s0[2] + s0[3] + s1[2] + s1[3];
            pa[nt][0] = pack_h2(s0[0], s0[1]);
            pa[nt][1] = pack_h2(s0[2], s0[3]);
            pa[nt][2] = pack_h2(s1[0], s1[1]);
            pa[nt][3] = pack_h2(s1[2], s1[3]);
        }

        // ---- O += P . V^T ----
        const uint32_t Vb = SV + buf * 67584;
        #pragma unroll
        for (int ct2 = 0; ct2 < 16; ct2++) {
            #pragma unroll
            for (int nt = 0; nt < 8; nt++) {
                uint32_t br[4];
                ldsm_x4t(br, Vb + (nt * 16 + vn) * 528 + (ct2 * 16 + vc) * 2);
                mma_f16f32(o[ct2 * 2],     pa[nt], br);
                mma_f16f32(o[ct2 * 2 + 1], pa[nt], br + 2);
            }
        }
        if (j < 31) CP_WAIT0();
        __syncthreads();
    }

    // row-sum reduce across quad lanes
    rs0 += __shfl_xor_sync(0xffffffffu, rs0, 1);
    rs0 += __shfl_xor_sync(0xffffffffu, rs0, 2);
    rs1 += __shfl_xor_sync(0xffffffffu, rs1, 1);
    rs1 += __shfl_xor_sync(0xffffffffu, rs1, 2);
    const float inv0 = 1.0f / rs0, inv1 = 1.0f / rs1;

    // epilogue: transpose via smem (reuse), out[b][c][m] = O/sum + x
    __syncthreads();
    float* epi = reinterpret_cast<float*>(dsm);
    const int r0 = 16 * wid + (lane >> 2);
    #pragma unroll
    for (int ct = 0; ct < 32; ct++) {
        int c = ct * 8 + (lane & 3) * 2;
        epi[r0 * 257 + c]           = o[ct][0] * inv0;
        epi[r0 * 257 + c + 1]       = o[ct][1] * inv0;
        epi[(r0 + 8) * 257 + c]     = o[ct][2] * inv1;
        epi[(r0 + 8) * 257 + c + 1] = o[ct][3] * inv1;
    }
    __syncthreads();
    const float* xb = x + (size_t)b * CIN * NPIX;
    float* ob = out + (size_t)b * CIN * NPIX;
    for (int i = tid; i < 256 * 128; i += 256) {
        int c = i >> 7, m = i & 127;
        size_t gidx = (size_t)(chalf * 256 + c) * NPIX + m0 + m;
        ob[gidx] = epi[m * 257 + c] + xb[gidx];
    }
}

// ---------------------------------------------------------------------------
extern "C" void kernel_launch(void* const* d_in, const int* in_sizes, int n_in,
                              void* d_out, int out_size)
{
    const float* x  = (const float*)d_in[0];
    const float* Wq = (const float*)d_in[1];
    const float* bq = (const float*)d_in[2];
    const float* Wk = (const float*)d_in[3];
    const float* bk = (const float*)d_in[4];
    const float* Wv = (const float*)d_in[5];
    const float* bv = (const float*)d_in[6];
    float* out = (float*)d_out;

    cudaFuncSetAttribute(proj_qkv_kernel, cudaFuncAttributeMaxDynamicSharedMemorySize, 73728);
    cudaFuncSetAttribute(attn_kernel,     cudaFuncAttributeMaxDynamicSharedMemorySize, 190464);

    convert_w_kernel<<<1280, 256>>>(Wq, Wk, Wv);
    transpose_x_kernel<<<dim3(NPIX / 64, CIN / 64, B), 256>>>(x);
    proj_qkv_kernel<<<dim3(NPIX / 128, 5, B), 256, 73728>>>(bq, bk, bv);
    attn_kernel<<<dim3(NPIX / 128, 2, B), 256, 190464>>>(x, out);
}

// round 13
// speedup vs baseline: 1.1949x; 1.0777x over previous
#include <cuda_runtime.h>
#include <cuda_bf16.h>
#include <cstdint>

#define NPIX 4096
#define CIN  512
#define B    4

__device__ __align__(16) __nv_bfloat16 g_q [(size_t)B * NPIX * 64];    // [b][n][d]
__device__ __align__(16) __nv_bfloat16 g_k [(size_t)B * NPIX * 64];    // [b][n][d]
__device__ __align__(16) __nv_bfloat16 g_v [(size_t)B * CIN * NPIX];   // [b][c][n]
__device__ __align__(16) __nv_bfloat16 g_wqk[128 * CIN];               // [q64;k64][c]
__device__ __align__(16) __nv_bfloat16 g_wv [CIN * CIN];               // [o][c]

// ------------------------------ helpers -----------------------------------
__device__ __forceinline__ uint32_t smem_u32(const void* p) {
    uint32_t a;
    asm("{ .reg .u64 t; cvta.to.shared.u64 t, %1; cvt.u32.u64 %0, t; }" : "=r"(a) : "l"(p));
    return a;
}
__device__ __forceinline__ void ldsm_x4(uint32_t* r, uint32_t a) {
    asm volatile("ldmatrix.sync.aligned.m8n8.x4.shared.b16 {%0,%1,%2,%3}, [%4];"
        : "=r"(r[0]), "=r"(r[1]), "=r"(r[2]), "=r"(r[3]) : "r"(a));
}
__device__ __forceinline__ void ldsm_x4t(uint32_t* r, uint32_t a) {
    asm volatile("ldmatrix.sync.aligned.m8n8.x4.trans.shared.b16 {%0,%1,%2,%3}, [%4];"
        : "=r"(r[0]), "=r"(r[1]), "=r"(r[2]), "=r"(r[3]) : "r"(a));
}
__device__ __forceinline__ void mma_bf16(float* d, const uint32_t* a, const uint32_t* b) {
    asm volatile("mma.sync.aligned.m16n8k16.row.col.f32.bf16.bf16.f32 "
        "{%0,%1,%2,%3},{%4,%5,%6,%7},{%8,%9},{%0,%1,%2,%3};"
        : "+f"(d[0]), "+f"(d[1]), "+f"(d[2]), "+f"(d[3])
        : "r"(a[0]), "r"(a[1]), "r"(a[2]), "r"(a[3]), "r"(b[0]), "r"(b[1]));
}
__device__ __forceinline__ void cp16(uint32_t dst, const void* src) {
    asm volatile("cp.async.cg.shared.global [%0], [%1], 16;" :: "r"(dst), "l"(src));
}
#define CP_COMMIT() asm volatile("cp.async.commit_group;" ::: "memory")
#define CP_WAIT0()  asm volatile("cp.async.wait_group 0;" ::: "memory")
#define STS32(a,v) asm volatile("st.shared.b32 [%0], %1;" :: "r"(a),"r"(v) : "memory")
__device__ __forceinline__ uint32_t pack_bf2(float lo, float hi) {
    uint32_t u;
    asm("cvt.rn.bf16x2.f32 %0, %1, %2;" : "=r"(u) : "f"(hi), "f"(lo));
    return u;
}

// -------------------------- weight convert ---------------------------------
__global__ void convert_w_kernel(const float* __restrict__ Wq, const float* __restrict__ Wk,
                                 const float* __restrict__ Wv) {
    int i = blockIdx.x * 256 + threadIdx.x;
    if (i < 64 * CIN) g_wqk[i] = __float2bfloat16(Wq[i]);
    else if (i < 128 * CIN) g_wqk[i] = __float2bfloat16(Wk[i - 64 * CIN]);
    else if (i < 128 * CIN + CIN * CIN) g_wv[i - 128 * CIN] = __float2bfloat16(Wv[i - 128 * CIN]);
}

// ------------- fused proj (no xT): C[out(128), n(128)] = W . x -------------
// A = W[out][c] (K-major, non-trans ldsm), B = x[c][n] native (trans ldsm).
// chunk 0 -> q|k (transposed epilogue via smem), chunks 1-4 -> v[b][c][n].
// smem: W 2x18432 | X 2x17408 (= 71680); chunk0 epilogue reuses as f32[128][129].
__global__ __launch_bounds__(256)
void proj_qkv_kernel(const float* __restrict__ x, const float* __restrict__ bq,
                     const float* __restrict__ bk, const float* __restrict__ bv) {
    extern __shared__ char dsm[];
    const uint32_t sb = smem_u32(dsm);
    const uint32_t SW = sb, SX = sb + 36864;
    const int tid = threadIdx.x, wid = tid >> 5, lane = tid & 31;
    const int n0 = blockIdx.x * 128, chunk = blockIdx.y, b = blockIdx.z;
    const __nv_bfloat16* gW = (chunk == 0) ? g_wqk : (g_wv + (size_t)(chunk - 1) * 128 * CIN);
    const float* gx = x + (size_t)b * CIN * NPIX + n0;

    auto ldW = [&](uint32_t dst, int kk) {
        for (int i = tid; i < 1024; i += 256) {
            int r = i >> 3, s = i & 7;
            cp16(dst + r * 144 + s * 16, gW + (size_t)r * CIN + kk * 64 + s * 8);
        }
    };
    // x chunk: 64 c-rows x 128 n fp32 -> bf16 smem [c][n], pitch 272, no transpose
    const int cl = tid >> 5, n2 = (tid & 31) * 2;
    auto ldx_regs = [&](uint32_t* r, int kk) {
        #pragma unroll
        for (int cp = 0; cp < 8; cp++) {
            const float* row = gx + (size_t)(kk * 64 + cl + cp * 8) * NPIX;
            #pragma unroll
            for (int np = 0; np < 2; np++) {
                float2 v = *reinterpret_cast<const float2*>(row + n2 + np * 64);
                r[cp * 2 + np] = pack_bf2(v.x, v.y);
            }
        }
    };
    auto stx = [&](uint32_t dstb, const uint32_t* r) {
        #pragma unroll
        for (int cp = 0; cp < 8; cp++)
            #pragma unroll
            for (int np = 0; np < 2; np++)
                STS32(dstb + (cl + cp * 8) * 272 + (n2 + np * 64) * 2, r[cp * 2 + np]);
    };

    uint32_t xr[16];
    ldW(SW, 0); CP_COMMIT();
    ldx_regs(xr, 0); stx(SX, xr);
    CP_WAIT0(); __syncthreads();

    const int ar = (lane & 7) + ((lane >> 3) & 1) * 8, ak = ((lane >> 4) & 1) * 8;
    const int vn = ((lane >> 3) & 1) * 8 + (lane & 7), vc = ((lane >> 4) & 1) * 8;
    float o[16][4] = {};

    for (int kk = 0; kk < 8; kk++) {
        const int buf = kk & 1;
        if (kk < 7) { ldW(SW + (buf ^ 1) * 18432, kk + 1); CP_COMMIT(); ldx_regs(xr, kk + 1); }
        const uint32_t Ab = SW + buf * 18432 + (16 * wid + ar) * 144 + ak * 2;
        const uint32_t Xb = SX + buf * 17408;
        uint32_t wa[4][4];
        #pragma unroll
        for (int kc = 0; kc < 4; kc++) ldsm_x4(wa[kc], Ab + kc * 32);
        #pragma unroll
        for (int nt = 0; nt < 8; nt++) {
            #pragma unroll
            for (int kc = 0; kc < 4; kc++) {
                uint32_t br[4];
                ldsm_x4t(br, Xb + (kc * 16 + vn) * 272 + (nt * 16 + vc) * 2);
                mma_bf16(o[nt * 2],     wa[kc], br);
                mma_bf16(o[nt * 2 + 1], wa[kc], br + 2);
            }
        }
        if (kk < 7) { stx(SX + (buf ^ 1) * 17408, xr); CP_WAIT0(); }
        __syncthreads();
    }

    const int r0 = 16 * wid + (lane >> 2);
    if (chunk == 0) {
        // stage (with bias) into f32 smem, then write q/k transposed+coalesced
        float* epi = reinterpret_cast<float*>(dsm);
        const float bb0 = (r0 < 64) ? __ldg(bq + r0) : __ldg(bk + r0 - 64);
        const float bb1 = (r0 + 8 < 64) ? __ldg(bq + r0 + 8) : __ldg(bk + r0 + 8 - 64);
        #pragma unroll
        for (int ot = 0; ot < 16; ot++) {
            int n = ot * 8 + (lane & 3) * 2;
            epi[r0 * 129 + n]           = o[ot][0] + bb0;
            epi[r0 * 129 + n + 1]       = o[ot][1] + bb0;
            epi[(r0 + 8) * 129 + n]     = o[ot][2] + bb1;
            epi[(r0 + 8) * 129 + n + 1] = o[ot][3] + bb1;
        }
        __syncthreads();
        for (int i = tid; i < 8192; i += 256) {
            int n = i >> 6, d2 = (i & 63) * 2;
            uint32_t pk = pack_bf2(epi[d2 * 129 + n], epi[(d2 + 1) * 129 + n]);
            __nv_bfloat16* base = (d2 < 64) ? g_q : g_k;
            *reinterpret_cast<uint32_t*>(base + ((size_t)b * NPIX + n0 + n) * 64 + (d2 & 63)) = pk;
        }
    } else {
        const int c0 = (chunk - 1) * 128;
        const float bb0 = __ldg(bv + c0 + r0), bb1 = __ldg(bv + c0 + r0 + 8);
        #pragma unroll
        for (int ot = 0; ot < 16; ot++) {
            int n = ot * 8 + (lane & 3) * 2;
            *reinterpret_cast<uint32_t*>(g_v + ((size_t)b * CIN + c0 + r0) * NPIX + n0 + n) =
                pack_bf2(o[ot][0] + bb0, o[ot][1] + bb0);
            *reinterpret_cast<uint32_t*>(g_v + ((size_t)b * CIN + c0 + r0 + 8) * NPIX + n0 + n) =
                pack_bf2(o[ot][2] + bb1, o[ot][3] + bb1);
        }
    }
}

// --------------------------- fused attention ------------------------------
// R7 engine: CTA 64m x 256c-half x b (grid 64x2x4), 128 threads = 4 warps,
// each 16m x 256c, n-tile 64, 2 CTAs/SM. V now [b][c][n] -> tile [256c][64n]
// pitch 144, NON-trans ldsm (bn/bk2 pattern). smem 90 KB:
// [SQK1 9216 | SK0 9216 | SV 2x36864]; Q smem recycled as K buf 1.
// Epilogue reuses smem as f32 epi[64][257].
__global__ __launch_bounds__(128, 2)
void attn_kernel(const float* __restrict__ x, float* __restrict__ out) {
    extern __shared__ char dsm[];
    const uint32_t sb = smem_u32(dsm);
    const uint32_t SQK1 = sb, SK0 = sb + 9216, SV = sb + 18432;
    const int tid = threadIdx.x, wid = tid >> 5, lane = tid & 31;
    const int m0 = blockIdx.x * 64, chalf = blockIdx.y, b = blockIdx.z;

    const __nv_bfloat16* gQ = g_q + ((size_t)b * NPIX + m0) * 64;
    const __nv_bfloat16* gK = g_k + (size_t)b * NPIX * 64;
    const __nv_bfloat16* gV = g_v + ((size_t)b * CIN + chalf * 256) * NPIX;

    auto ldK = [&](uint32_t dst, int jj) {
        const __nv_bfloat16* src = gK + (size_t)jj * 64 * 64;
        for (int i = tid; i < 512; i += 128) {
            int r = i >> 3, s = i & 7;
            cp16(dst + r * 144 + s * 16, src + (size_t)r * 64 + s * 8);
        }
    };
    auto ldV = [&](uint32_t dst, int jj) {
        const __nv_bfloat16* src = gV + (size_t)jj * 64;   // [c][n]: row stride NPIX
        for (int i = tid; i < 2048; i += 128) {
            int r = i >> 3, s = i & 7;
            cp16(dst + r * 144 + s * 16, src + (size_t)r * NPIX + s * 8);
        }
    };
    // prologue: Q (64m x 64d into SQK1), K0, V0
    for (int i = tid; i < 512; i += 128) {
        int r = i >> 3, s = i & 7;
        cp16(SQK1 + r * 144 + s * 16, gQ + (size_t)r * 64 + s * 8);
    }
    ldK(SK0, 0); ldV(SV, 0);
    CP_COMMIT(); CP_WAIT0(); __syncthreads();

    const int ar = (lane & 7) + ((lane >> 3) & 1) * 8, ak = ((lane >> 4) & 1) * 8;
    const int bn = ((lane >> 4) & 1) * 8 + (lane & 7), bk2 = ((lane >> 3) & 1) * 8;

    // hoist Q fragments; Q smem becomes K buffer 1
    uint32_t qa[4][4];
    {
        const uint32_t Ab = SQK1 + (wid * 16 + ar) * 144 + ak * 2;
        #pragma unroll
        for (int kc = 0; kc < 4; kc++) ldsm_x4(qa[kc], Ab + kc * 32);
    }
    __syncthreads();

    float o[32][4] = {};
    float rs[2] = {};

    for (int j = 0; j < 64; j++) {
        const int buf = j & 1;
        const uint32_t Kb = buf ? SQK1 : SK0;
        const uint32_t Vb = SV + buf * 36864;
        if (j < 63) {
            ldK(buf ? SK0 : SQK1, j + 1);
            ldV(SV + (buf ^ 1) * 36864, j + 1);
            CP_COMMIT();
        }
        #pragma unroll
        for (int nt = 0; nt < 4; nt++) {
            // S = Q.K^T (16m x 16n)
            float s[8] = {};
            #pragma unroll
            for (int kc = 0; kc < 4; kc++) {
                uint32_t br[4];
                ldsm_x4(br, Kb + (nt * 16 + bn) * 144 + (kc * 16 + bk2) * 2);
                mma_bf16(s,     qa[kc], br);
                mma_bf16(s + 4, qa[kc], br + 2);
            }
            // exp + rowsum + pack
            #pragma unroll
            for (int t = 0; t < 8; t++) s[t] = __expf(s[t]);
            rs[0] += s[0] + s[1] + s[4] + s[5];
            rs[1] += s[2] + s[3] + s[6] + s[7];
            uint32_t pa[4];
            pa[0] = pack_bf2(s[0], s[1]);
            pa[1] = pack_bf2(s[2], s[3]);
            pa[2] = pack_bf2(s[4], s[5]);
            pa[3] = pack_bf2(s[6], s[7]);
            // O += P.V^T over 256 c; V tile [c][n] pitch 144, non-trans
            #pragma unroll
            for (int ct = 0; ct < 16; ct++) {
                uint32_t vfr[4];
                ldsm_x4(vfr, Vb + (ct * 16 + bn) * 144 + (nt * 16 + bk2) * 2);
                mma_bf16(o[ct * 2],     pa, vfr);
                mma_bf16(o[ct * 2 + 1], pa, vfr + 2);
            }
        }
        if (j < 63) CP_WAIT0();
        __syncthreads();
    }

    // quad-lane rowsum reduce
    float inv[2];
    #pragma unroll
    for (int h = 0; h < 2; h++) {
        float r = rs[h];
        r += __shfl_xor_sync(0xffffffffu, r, 1);
        r += __shfl_xor_sync(0xffffffffu, r, 2);
        inv[h] = 1.0f / r;
    }

    // epilogue: transpose through smem, out[b][c][m] = O/sum + x
    float* epi = reinterpret_cast<float*>(dsm);
    const int r0 = wid * 16 + (lane >> 2);
    #pragma unroll
    for (int ot = 0; ot < 32; ot++) {
        int c = ot * 8 + (lane & 3) * 2;
        epi[r0 * 257 + c]           = o[ot][0] * inv[0];
        epi[r0 * 257 + c + 1]       = o[ot][1] * inv[0];
        epi[(r0 + 8) * 257 + c]     = o[ot][2] * inv[1];
        epi[(r0 + 8) * 257 + c + 1] = o[ot][3] * inv[1];
    }
    __syncthreads();
    const float* xb = x + (size_t)b * CIN * NPIX;
    float* ob = out + (size_t)b * CIN * NPIX;
    for (int i = tid; i < 256 * 64; i += 128) {
        int c = i >> 6, m = i & 63;
        size_t gidx = (size_t)(chalf * 256 + c) * NPIX + m0 + m;
        ob[gidx] = epi[m * 257 + c] + xb[gidx];
    }
}

// ---------------------------------------------------------------------------
extern "C" void kernel_launch(void* const* d_in, const int* in_sizes, int n_in,
                              void* d_out, int out_size)
{
    const float* x  = (const float*)d_in[0];
    const float* Wq = (const float*)d_in[1];
    const float* bq = (const float*)d_in[2];
    const float* Wk = (const float*)d_in[3];
    const float* bk = (const float*)d_in[4];
    const float* Wv = (const float*)d_in[5];
    const float* bv = (const float*)d_in[6];
    float* out = (float*)d_out;

    cudaFuncSetAttribute(proj_qkv_kernel, cudaFuncAttributeMaxDynamicSharedMemorySize, 71680);
    cudaFuncSetAttribute(attn_kernel,     cudaFuncAttributeMaxDynamicSharedMemorySize, 92160);

    convert_w_kernel<<<1280, 256>>>(Wq, Wk, Wv);
    proj_qkv_kernel<<<dim3(NPIX / 128, 5, B), 256, 71680>>>(x, bq, bk, bv);
    attn_kernel<<<dim3(NPIX / 64, 2, B), 128, 92160>>>(x, out);
}